// round 10
// baseline (speedup 1.0000x reference)
#include <cuda_runtime.h>
#include <cuda_fp16.h>
#include <cstdint>
#include <cstddef>

#define CH   40
#define TT   2000
#define LL   256
#define NB   64
#define NEGF (-1.0e30f)
#define POSF (1.0e30f)
#define LOG2E 1.4426950408889634f
#define LN2   0.6931471805599453f

// ---------------- device scratch ----------------
__device__ unsigned long long g_maskkeys[NB * 256];
__device__ int   g_labels[NB * 256];
__device__ int   g_tlen[NB];
__device__ float g_em[(size_t)NB * TT * 256];
__device__ float g_loss[NB];
__device__ unsigned int g_done;

// ---------------- PTX helpers ----------------
__device__ __forceinline__ float ex2f(float x) {
    float r; asm("ex2.approx.ftz.f32 %0, %1;" : "=f"(r) : "f"(x)); return r;
}
__device__ __forceinline__ float lg2f(float x) {
    float r; asm("lg2.approx.ftz.f32 %0, %1;" : "=f"(r) : "f"(x)); return r;
}
__device__ __forceinline__ unsigned long long pk2(float x, float y) {
    unsigned long long r;
    asm("mov.b64 %0, {%1, %2};" : "=l"(r) : "f"(x), "f"(y));
    return r;
}
__device__ __forceinline__ void ffma2(unsigned long long &a, unsigned long long m, unsigned long long d) {
    asm("fma.rn.f32x2 %0, %1, %2, %3;" : "=l"(a) : "l"(m), "l"(d), "l"(a));
}
__device__ __forceinline__ void up2(unsigned long long v, float &x, float &y) {
    asm("mov.b64 {%0, %1}, %2;" : "=f"(x), "=f"(y) : "l"(v));
}

// =====================================================================
// Kernel 0: no-op (keeps ncu capture index on k_ctc)
// =====================================================================
__global__ void k_nop() {}

// =====================================================================
// Kernel 1: preprocessing (verified exact)
// =====================================================================
__global__ void k_preprocess(const int* __restrict__ targets) {
    const int n = blockIdx.x;
    const int l = threadIdx.x;

    __shared__ unsigned long long skey[256];
    __shared__ int sscan[256];
    __shared__ int sinv[256];

    if (n == 0 && l == 0) g_done = 0;

    unsigned long long key = 0ull;
#pragma unroll
    for (int c = 0; c < CH; c++) {
        key |= ((unsigned long long)(targets[(n * CH + c) * LL + l] & 1)) << (CH - 1 - c);
    }
    skey[l] = (key << 8) | (unsigned long long)l;
    __syncthreads();

    for (int k = 2; k <= 256; k <<= 1) {
        for (int j = k >> 1; j > 0; j >>= 1) {
            int ixj = l ^ j;
            if (ixj > l) {
                unsigned long long a = skey[l], b = skey[ixj];
                bool up = ((l & k) == 0);
                if ((a > b) == up) { skey[l] = b; skey[ixj] = a; }
            }
            __syncthreads();
        }
    }

    unsigned long long kv = skey[l] >> 8;
    unsigned long long kvp = (l > 0) ? (skey[l - 1] >> 8) : 0ull;
    int head = (l == 0 || kv != kvp) ? 1 : 0;
    sscan[l] = head;
    __syncthreads();
    for (int off = 1; off < 256; off <<= 1) {
        int v = sscan[l];
        int w = (l >= off) ? sscan[l - off] : 0;
        __syncthreads();
        sscan[l] = v + w;
        __syncthreads();
    }
    const int u   = sscan[255];
    const int uid = sscan[l] - 1;
    const int orig = (int)(skey[l] & 255ull);
    int inv2 = uid + 1; if (inv2 == u) inv2 = 0;
    sinv[orig] = inv2;
    if (head) g_maskkeys[n * 256 + inv2] = kv;
    __syncthreads();

    int flag = (l > 0 && sinv[l] != sinv[l - 1]) ? 1 : 0;
    int myinv = sinv[l];
    sscan[l] = flag;
    __syncthreads();
    for (int off = 1; off < 256; off <<= 1) {
        int v = sscan[l];
        int w = (l >= off) ? sscan[l - off] : 0;
        __syncthreads();
        sscan[l] = v + w;
        __syncthreads();
    }
    if (flag) g_labels[n * 256 + (sscan[l] - 1)] = myinv;
    if (l == 0) g_tlen[n] = sscan[255];
}

// =====================================================================
// Kernel 2: emission v3 — 128 threads, each owns 2 j-columns (j, j+128)
// sharing every staged d2 load (LDS:FMA ratio halved). Coalesced stores.
// =====================================================================
#define TTILE 32
__global__ void __launch_bounds__(128) k_emission(const float* __restrict__ lp) {
    const int n  = blockIdx.y;
    const int t0 = blockIdx.x * TTILE;
    const int j0 = threadIdx.x;          // 0..127
    const int j1 = j0 + 128;

    __shared__ __align__(16) float d2f[CH][TTILE];
    __shared__ float sbase[TTILE];
    __shared__ float sblank[TTILE];

    const float* lp0 = lp + ((size_t)n * 2 + 0) * CH * TT;
    const float* lp1 = lp + ((size_t)n * 2 + 1) * CH * TT;

    // stage d2f: 1280 entries, 10 passes of 128 threads
#pragma unroll
    for (int it = 0; it < 10; it++) {
        int idx = it * 128 + j0;
        int c = idx >> 5;
        int tt = idx & 31;
        int t = t0 + tt;
        float v = 0.0f;
        if (t < TT) {
            float x0 = __ldg(lp0 + c * TT + t);
            float x1 = __ldg(lp1 + c * TT + t);
            v = (x1 - x0) * LOG2E;
        }
        d2f[c][tt] = v;
    }
    if (j0 < TTILE) {
        int t = t0 + j0;
        float b = 0.0f, bl = 0.0f;
        if (t < TT) {
#pragma unroll
            for (int c = 0; c < CH; c++) b += __ldg(lp0 + c * TT + t);
            bl = __ldg(lp1 + t);
        }
        sbase[j0]  = b * LOG2E;
        sblank[j0] = bl * LOG2E;
    }
    __syncthreads();

    const unsigned long long mk0 = g_maskkeys[n * 256 + j0];
    const unsigned long long mk1 = g_maskkeys[n * 256 + j1];

    unsigned long long acc0[TTILE / 2], acc1[TTILE / 2];
    const unsigned long long* basep = (const unsigned long long*)sbase;
#pragma unroll
    for (int tp = 0; tp < TTILE / 2; tp++) { acc0[tp] = basep[tp]; acc1[tp] = basep[tp]; }

#pragma unroll 8
    for (int c = 0; c < CH; c++) {
        float m0 = (float)((mk0 >> (CH - 1 - c)) & 1ull);
        float m1 = (float)((mk1 >> (CH - 1 - c)) & 1ull);
        unsigned long long mm0 = pk2(m0, m0);
        unsigned long long mm1 = pk2(m1, m1);
        const ulonglong2* drow = (const ulonglong2*)&d2f[c][0];
#pragma unroll
        for (int tq = 0; tq < TTILE / 4; tq++) {
            ulonglong2 d = drow[tq];
            ffma2(acc0[2 * tq],     mm0, d.x);
            ffma2(acc0[2 * tq + 1], mm0, d.y);
            ffma2(acc1[2 * tq],     mm1, d.x);
            ffma2(acc1[2 * tq + 1], mm1, d.y);
        }
    }

    float* outb0 = g_em + ((size_t)n * TT + t0) * 256 + j0;
    float* outb1 = g_em + ((size_t)n * TT + t0) * 256 + j1;
#pragma unroll
    for (int tp = 0; tp < TTILE / 2; tp++) {
        int te = 2 * tp, to = 2 * tp + 1;
        float v0, v1;
        up2(acc0[tp], v0, v1);
        if (j0 == 0) { v0 = sblank[te]; v1 = sblank[to]; }
        if (t0 + te < TT) outb0[(size_t)te * 256] = v0;
        if (t0 + to < TT) outb0[(size_t)to * 256] = v1;
        float w0, w1;
        up2(acc1[tp], w0, w1);
        if (t0 + te < TT) outb1[(size_t)te * 256] = w0;
        if (t0 + to < TT) outb1[(size_t)to * 256] = w1;
    }
}

// =====================================================================
// Kernel 3: CTC forward — 5 warps, 2 state-pairs per thread, halo
// windows. f16x2-packed MUFU: 3 h2exp2 + 2 h2log2 per step. Fused mean.
// =====================================================================
__device__ __forceinline__ void stage_rows5(float (*sEm)[256], const float* emn,
                                            int r0, int tid) {
#pragma unroll
    for (int i = 0; i < 4; i++) {
        int c = tid + i * 160;
        if (c < 512) {
            int r = r0 + (c >> 6);
            int off = (c & 63) * 4;
            if (r < TT) {
                uint32_t dst = (uint32_t)__cvta_generic_to_shared(&sEm[r & 31][off]);
                const float* src = emn + (size_t)r * 256 + off;
                asm volatile("cp.async.cg.shared.global [%0], [%1], 16;\n"
                             :: "r"(dst), "l"(src));
            }
        }
    }
    asm volatile("cp.async.commit_group;\n" ::: "memory");
}

__global__ void __launch_bounds__(160) k_ctc(float* __restrict__ d_out) {
    const int n = blockIdx.x;
    const int tid = threadIdx.x;
    const int w = tid >> 5;
    const int l = tid & 31;
    const int q0 = 48 * w + 2 * l;
    const int q1 = q0 + 1;

    __shared__ __align__(16) float sEm[32][256];
    __shared__ __align__(16) float4 EX[2][5][8];
    __shared__ __align__(8)  float2 AF[256];

    const int tlen = g_tlen[n];
    const float* emn = g_em + (size_t)n * TT * 256;

    int lab0 = 0, lab1 = 0;
    float skip0 = NEGF, skip1 = NEGF;
    if (q0 < tlen) {
        lab0 = g_labels[n * 256 + q0];
        if (q0 >= 1) {
            int lm = g_labels[n * 256 + q0 - 1];
            if (lab0 != 0 && lab0 != lm) skip0 = POSF;
        }
    }
    if (q1 < tlen) {
        lab1 = g_labels[n * 256 + q1];
        int lm = g_labels[n * 256 + q1 - 1];
        if (lab1 != 0 && lab1 != lm) skip1 = POSF;
    }
    const float edge1 = (tid == 0) ? NEGF : POSF;

    float e0 = NEGF, o0 = NEGF, e1 = NEGF, o1 = NEGF;
    if (tid == 0) {
        e0 = __ldg(emn + 0);
        o0 = __ldg(emn + lab0);
    }

    stage_rows5(sEm, emn, 1, tid);
    stage_rows5(sEm, emn, 9, tid);

#define DO_STEP(tt)                                                         \
    do {                                                                    \
        const float* srow = &sEm[(tt) & 31][0];                             \
        float emE = srow[0];                                                \
        float em0 = srow[lab0];                                             \
        float em1 = srow[lab1];                                             \
        float aOp = __shfl_up_sync(0xffffffffu, o1, 1);                     \
        aOp = fminf(aOp, edge1);                                            \
        float cc0 = fminf(aOp, skip0);                                      \
        float mE0 = fmaxf(e0, aOp);                                         \
        float dE0 = fminf(e0, aOp) - mE0;                                   \
        float hi0 = fmaxf(o0, e0), lo0 = fminf(o0, e0);                     \
        float mO0 = fmaxf(hi0, cc0);                                        \
        float se0 = fminf(hi0, fmaxf(lo0, cc0)) - mO0;                      \
        float th0 = fminf(lo0, cc0) - mO0;                                  \
        float cc1 = fminf(o0, skip1);                                       \
        float mE1 = fmaxf(e1, o0);                                          \
        float dE1 = fminf(e1, o0) - mE1;                                    \
        float hi1 = fmaxf(o1, e1), lo1 = fminf(o1, e1);                     \
        float mO1 = fmaxf(hi1, cc1);                                        \
        float se1 = fminf(hi1, fmaxf(lo1, cc1)) - mO1;                      \
        float th1 = fminf(lo1, cc1) - mO1;                                  \
        __half2 hd = h2exp2(__floats2half2_rn(dE0, dE1));                   \
        __half2 h0 = h2exp2(__floats2half2_rn(se0, th0));                   \
        __half2 h1 = h2exp2(__floats2half2_rn(se1, th1));                   \
        float2 fd = __half22float2(hd);                                     \
        float2 f0 = __half22float2(h0);                                     \
        float2 f1 = __half22float2(h1);                                     \
        float sEx0 = 1.0f + fd.x;                                           \
        float sEx1 = 1.0f + fd.y;                                           \
        float sO0 = 1.0f + f0.x + f0.y;                                     \
        float sO1 = 1.0f + f1.x + f1.y;                                     \
        __half2 le = h2log2(__floats2half2_rn(sEx0, sEx1));                 \
        __half2 lo_ = h2log2(__floats2half2_rn(sO0, sO1));                  \
        float2 fle = __half22float2(le);                                    \
        float2 flo = __half22float2(lo_);                                   \
        e0 = (mE0 + emE) + fle.x;                                           \
        e1 = (mE1 + emE) + fle.y;                                           \
        o0 = (mO0 + em0) + flo.x;                                           \
        o1 = (mO1 + em1) + flo.y;                                           \
    } while (0)

    int buf = 0;
    for (int b = 0; b < 249; b++) {
        stage_rows5(sEm, emn, 8 * b + 17, tid);
        asm volatile("cp.async.wait_group 2;\n" ::: "memory");
        if (l >= 24) EX[buf][w][l - 24] = make_float4(e0, o0, e1, o1);
        __syncthreads();
        if (w > 0 && l < 8) {
            float4 v = EX[buf][w - 1][l];
            e0 = v.x; o0 = v.y; e1 = v.z; o1 = v.w;
        }
        buf ^= 1;

        const int t0 = 8 * b + 1;
#pragma unroll
        for (int s = 0; s < 8; s++) DO_STEP(t0 + s);
    }

    {
        asm volatile("cp.async.wait_group 0;\n" ::: "memory");
        if (l >= 24) EX[buf][w][l - 24] = make_float4(e0, o0, e1, o1);
        __syncthreads();
        if (w > 0 && l < 8) {
            float4 v = EX[buf][w - 1][l];
            e0 = v.x; o0 = v.y; e1 = v.z; o1 = v.w;
        }
#pragma unroll
        for (int s = 0; s < 7; s++) DO_STEP(1993 + s);
    }
#undef DO_STEP

    if (w == 0 || l >= 7) {
        AF[q0] = make_float2(e0, o0);
        AF[q1] = make_float2(e1, o1);
    }
    __syncthreads();

    if (tid == 0) {
        float ea = AF[tlen].x;
        float eb = AF[(tlen >= 1) ? tlen - 1 : 0].y;
        float m = fmaxf(ea, eb);
        float l2 = m + lg2f(ex2f(ea - m) + ex2f(eb - m));
        g_loss[n] = -l2 * LN2;
        __threadfence();
        unsigned int tk = atomicAdd(&g_done, 1u);
        if (tk == NB - 1) {
            __threadfence();
            volatile float* gl = g_loss;
            float s = 0.0f;
            for (int i = 0; i < NB; i++) s += gl[i];
            d_out[0] = s * (1.0f / (float)NB);
        }
    }
}

// =====================================================================
extern "C" void kernel_launch(void* const* d_in, const int* in_sizes, int n_in,
                              void* d_out, int out_size) {
    const float* lp = (const float*)d_in[0];
    const int*   tg = (const int*)d_in[1];
    if (n_in >= 2 && in_sizes[0] == NB * CH * LL) {
        lp = (const float*)d_in[1];
        tg = (const int*)d_in[0];
    }

    k_nop<<<1, 32>>>();
    k_preprocess<<<NB, 256>>>(tg);
    dim3 g2((TT + TTILE - 1) / TTILE, NB);
    k_emission<<<g2, 128>>>(lp);
    k_ctc<<<NB, 160>>>((float*)d_out);
}

// round 11
// speedup vs baseline: 1.5191x; 1.5191x over previous
#include <cuda_runtime.h>
#include <cstdint>
#include <cstddef>

#define CH   40
#define TT   2000
#define LL   256
#define NB   64
#define NEGF (-1.0e30f)
#define POSF (1.0e30f)
#define LOG2E 1.4426950408889634f
#define LN2   0.6931471805599453f

// lg2(1+u) ~ poly(x), x = u-1, u in [0,2]
#define D0 0.999835f
#define D1 0.721619f
#define D2 (-0.177414f)
#define D3 0.058070f
#define D4 (-0.029748f)
#define D5 0.0127536f

// ---------------- device scratch ----------------
__device__ unsigned long long g_maskkeys[NB * 256];
__device__ int   g_labels[NB * 256];
__device__ int   g_tlen[NB];
__device__ float g_em[(size_t)NB * TT * 256];
__device__ float g_loss[NB];
__device__ unsigned int g_done;

// ---------------- PTX helpers ----------------
__device__ __forceinline__ float ex2f(float x) {
    float r; asm("ex2.approx.ftz.f32 %0, %1;" : "=f"(r) : "f"(x)); return r;
}
__device__ __forceinline__ float lg2f(float x) {
    float r; asm("lg2.approx.ftz.f32 %0, %1;" : "=f"(r) : "f"(x)); return r;
}
__device__ __forceinline__ unsigned long long pk2(float x, float y) {
    unsigned long long r;
    asm("mov.b64 %0, {%1, %2};" : "=l"(r) : "f"(x), "f"(y));
    return r;
}
__device__ __forceinline__ void ffma2(unsigned long long &a, unsigned long long m, unsigned long long d) {
    asm("fma.rn.f32x2 %0, %1, %2, %3;" : "=l"(a) : "l"(m), "l"(d), "l"(a));
}
__device__ __forceinline__ void up2(unsigned long long v, float &x, float &y) {
    asm("mov.b64 {%0, %1}, %2;" : "=f"(x), "=f"(y) : "l"(v));
}

// =====================================================================
// Kernel 0: no-op (keeps ncu capture index on k_ctc)
// =====================================================================
__global__ void k_nop() {}

// =====================================================================
// Kernel 1: preprocessing (verified exact)
// =====================================================================
__global__ void k_preprocess(const int* __restrict__ targets) {
    const int n = blockIdx.x;
    const int l = threadIdx.x;

    __shared__ unsigned long long skey[256];
    __shared__ int sscan[256];
    __shared__ int sinv[256];

    if (n == 0 && l == 0) g_done = 0;

    unsigned long long key = 0ull;
#pragma unroll
    for (int c = 0; c < CH; c++) {
        key |= ((unsigned long long)(targets[(n * CH + c) * LL + l] & 1)) << (CH - 1 - c);
    }
    skey[l] = (key << 8) | (unsigned long long)l;
    __syncthreads();

    for (int k = 2; k <= 256; k <<= 1) {
        for (int j = k >> 1; j > 0; j >>= 1) {
            int ixj = l ^ j;
            if (ixj > l) {
                unsigned long long a = skey[l], b = skey[ixj];
                bool up = ((l & k) == 0);
                if ((a > b) == up) { skey[l] = b; skey[ixj] = a; }
            }
            __syncthreads();
        }
    }

    unsigned long long kv = skey[l] >> 8;
    unsigned long long kvp = (l > 0) ? (skey[l - 1] >> 8) : 0ull;
    int head = (l == 0 || kv != kvp) ? 1 : 0;
    sscan[l] = head;
    __syncthreads();
    for (int off = 1; off < 256; off <<= 1) {
        int v = sscan[l];
        int w = (l >= off) ? sscan[l - off] : 0;
        __syncthreads();
        sscan[l] = v + w;
        __syncthreads();
    }
    const int u   = sscan[255];
    const int uid = sscan[l] - 1;
    const int orig = (int)(skey[l] & 255ull);
    int inv2 = uid + 1; if (inv2 == u) inv2 = 0;
    sinv[orig] = inv2;
    if (head) g_maskkeys[n * 256 + inv2] = kv;
    __syncthreads();

    int flag = (l > 0 && sinv[l] != sinv[l - 1]) ? 1 : 0;
    int myinv = sinv[l];
    sscan[l] = flag;
    __syncthreads();
    for (int off = 1; off < 256; off <<= 1) {
        int v = sscan[l];
        int w = (l >= off) ? sscan[l - off] : 0;
        __syncthreads();
        sscan[l] = v + w;
        __syncthreads();
    }
    if (flag) g_labels[n * 256 + (sscan[l] - 1)] = myinv;
    if (l == 0) g_tlen[n] = sscan[255];
}

// =====================================================================
// Kernel 2: emission v3 (kept — measured ~66us)
// =====================================================================
#define TTILE 32
__global__ void __launch_bounds__(128) k_emission(const float* __restrict__ lp) {
    const int n  = blockIdx.y;
    const int t0 = blockIdx.x * TTILE;
    const int j0 = threadIdx.x;
    const int j1 = j0 + 128;

    __shared__ __align__(16) float d2f[CH][TTILE];
    __shared__ float sbase[TTILE];
    __shared__ float sblank[TTILE];

    const float* lp0 = lp + ((size_t)n * 2 + 0) * CH * TT;
    const float* lp1 = lp + ((size_t)n * 2 + 1) * CH * TT;

#pragma unroll
    for (int it = 0; it < 10; it++) {
        int idx = it * 128 + j0;
        int c = idx >> 5;
        int tt = idx & 31;
        int t = t0 + tt;
        float v = 0.0f;
        if (t < TT) {
            float x0 = __ldg(lp0 + c * TT + t);
            float x1 = __ldg(lp1 + c * TT + t);
            v = (x1 - x0) * LOG2E;
        }
        d2f[c][tt] = v;
    }
    if (j0 < TTILE) {
        int t = t0 + j0;
        float b = 0.0f, bl = 0.0f;
        if (t < TT) {
#pragma unroll
            for (int c = 0; c < CH; c++) b += __ldg(lp0 + c * TT + t);
            bl = __ldg(lp1 + t);
        }
        sbase[j0]  = b * LOG2E;
        sblank[j0] = bl * LOG2E;
    }
    __syncthreads();

    const unsigned long long mk0 = g_maskkeys[n * 256 + j0];
    const unsigned long long mk1 = g_maskkeys[n * 256 + j1];

    unsigned long long acc0[TTILE / 2], acc1[TTILE / 2];
    const unsigned long long* basep = (const unsigned long long*)sbase;
#pragma unroll
    for (int tp = 0; tp < TTILE / 2; tp++) { acc0[tp] = basep[tp]; acc1[tp] = basep[tp]; }

#pragma unroll 8
    for (int c = 0; c < CH; c++) {
        float m0 = (float)((mk0 >> (CH - 1 - c)) & 1ull);
        float m1 = (float)((mk1 >> (CH - 1 - c)) & 1ull);
        unsigned long long mm0 = pk2(m0, m0);
        unsigned long long mm1 = pk2(m1, m1);
        const ulonglong2* drow = (const ulonglong2*)&d2f[c][0];
#pragma unroll
        for (int tq = 0; tq < TTILE / 4; tq++) {
            ulonglong2 d = drow[tq];
            ffma2(acc0[2 * tq],     mm0, d.x);
            ffma2(acc0[2 * tq + 1], mm0, d.y);
            ffma2(acc1[2 * tq],     mm1, d.x);
            ffma2(acc1[2 * tq + 1], mm1, d.y);
        }
    }

    float* outb0 = g_em + ((size_t)n * TT + t0) * 256 + j0;
    float* outb1 = g_em + ((size_t)n * TT + t0) * 256 + j1;
#pragma unroll
    for (int tp = 0; tp < TTILE / 2; tp++) {
        int te = 2 * tp, to = 2 * tp + 1;
        float v0, v1;
        up2(acc0[tp], v0, v1);
        if (j0 == 0) { v0 = sblank[te]; v1 = sblank[to]; }
        if (t0 + te < TT) outb0[(size_t)te * 256] = v0;
        if (t0 + to < TT) outb0[(size_t)to * 256] = v1;
        float w0, w1;
        up2(acc1[tp], w0, w1);
        if (t0 + te < TT) outb1[(size_t)te * 256] = w0;
        if (t0 + to < TT) outb1[(size_t)to * 256] = w1;
    }
}

// =====================================================================
// Kernel 3: CTC forward — 4 warps (one per SMSP), 3 pairs per thread.
// Warp w covers pairs [72w, 72w+96), 24-pair halo -> 8-step windows.
// Same verified math as R9 (poly even / MUFU-lg2 odd). Fused mean.
// =====================================================================
__device__ __forceinline__ float lg2_poly(float u) {   // lg2(1+u), u in [0,2]
    float x = u - 1.0f;
    float x2 = x * x;
    float p = fmaf(D5, x, D4);
    float q = fmaf(D3, x, D2);
    float r = fmaf(D1, x, D0);
    p = fmaf(p, x2, q);
    return fmaf(p, x2, r);
}

__device__ __forceinline__ void stage_rows4(float (*sEm)[256], const float* emn,
                                            int r0, int tid) {
#pragma unroll
    for (int i = 0; i < 4; i++) {
        int c = tid + i * 128;
        int r = r0 + (c >> 6);
        int off = (c & 63) * 4;
        if (r < TT) {
            uint32_t dst = (uint32_t)__cvta_generic_to_shared(&sEm[r & 31][off]);
            const float* src = emn + (size_t)r * 256 + off;
            asm volatile("cp.async.cg.shared.global [%0], [%1], 16;\n"
                         :: "r"(dst), "l"(src));
        }
    }
    asm volatile("cp.async.commit_group;\n" ::: "memory");
}

__global__ void __launch_bounds__(128) k_ctc(float* __restrict__ d_out) {
    const int n = blockIdx.x;
    const int tid = threadIdx.x;
    const int w = tid >> 5;
    const int l = tid & 31;
    const int qA = 72 * w + 3 * l;    // pairs qA, qA+1, qA+2
    const int qB = qA + 1;
    const int qC = qA + 2;

    __shared__ __align__(16) float sEm[32][256];
    __shared__ __align__(16) float  EX[2][4][8][6];   // boundary exchange (3 pairs)
    __shared__ __align__(8)  float2 AF[256];

    const int tlen = g_tlen[n];
    const float* emn = g_em + (size_t)n * TT * 256;

    int labA = 0, labB = 0, labC = 0;
    float skipA = NEGF, skipB = NEGF, skipC = NEGF;
    if (qA < tlen) {
        labA = g_labels[n * 256 + qA];
        if (qA >= 1) {
            int lm = g_labels[n * 256 + qA - 1];
            if (labA != 0 && labA != lm) skipA = POSF;
        }
    }
    if (qB < tlen) {
        labB = g_labels[n * 256 + qB];
        int lm = g_labels[n * 256 + qB - 1];
        if (labB != 0 && labB != lm) skipB = POSF;
    }
    if (qC < tlen) {
        labC = g_labels[n * 256 + qC];
        int lm = g_labels[n * 256 + qC - 1];
        if (labC != 0 && labC != lm) skipC = POSF;
    }
    const float edge1 = (tid == 0) ? NEGF : POSF;

    float e0 = NEGF, o0 = NEGF, e1 = NEGF, o1 = NEGF, e2 = NEGF, o2 = NEGF;
    if (tid == 0) {
        e0 = __ldg(emn + 0);
        o0 = __ldg(emn + labA);
    }

    stage_rows4(sEm, emn, 1, tid);
    stage_rows4(sEm, emn, 9, tid);

#define DO_STEP(tt)                                                         \
    do {                                                                    \
        const float* srow = &sEm[(tt) & 31][0];                             \
        float emE = srow[0];                                                \
        float emA = srow[labA];                                             \
        float emB = srow[labB];                                             \
        float emC = srow[labC];                                             \
        float oPrev = __shfl_up_sync(0xffffffffu, o2, 1);                   \
        oPrev = fminf(oPrev, edge1);                                        \
        float o0o = o0, o1o = o1;                                           \
        /* pair A: left odd = oPrev */                                      \
        float ccA = fminf(oPrev, skipA);                                    \
        float mEA = fmaxf(e0, oPrev);                                       \
        float dEA = fminf(e0, oPrev) - mEA;                                 \
        float hiA = fmaxf(o0, e0), loA = fminf(o0, e0);                     \
        float mOA = fmaxf(hiA, ccA);                                        \
        float seA = fminf(hiA, fmaxf(loA, ccA)) - mOA;                      \
        float thA = fminf(loA, ccA) - mOA;                                  \
        /* pair B: left odd = o0 (old) */                                   \
        float ccB = fminf(o0o, skipB);                                      \
        float mEB = fmaxf(e1, o0o);                                         \
        float dEB = fminf(e1, o0o) - mEB;                                   \
        float hiB = fmaxf(o1, e1), loB = fminf(o1, e1);                     \
        float mOB = fmaxf(hiB, ccB);                                        \
        float seB = fminf(hiB, fmaxf(loB, ccB)) - mOB;                      \
        float thB = fminf(loB, ccB) - mOB;                                  \
        /* pair C: left odd = o1 (old) */                                   \
        float ccC = fminf(o1o, skipC);                                      \
        float mEC = fmaxf(e2, o1o);                                         \
        float dEC = fminf(e2, o1o) - mEC;                                   \
        float hiC = fmaxf(o2, e2), loC = fminf(o2, e2);                     \
        float mOC = fmaxf(hiC, ccC);                                        \
        float seC = fminf(hiC, fmaxf(loC, ccC)) - mOC;                      \
        float thC = fminf(loC, ccC) - mOC;                                  \
        float uEA = ex2f(dEA);                                              \
        float uOA = 1.0f + ex2f(seA) + ex2f(thA);                           \
        float uEB = ex2f(dEB);                                              \
        float uOB = 1.0f + ex2f(seB) + ex2f(thB);                           \
        float uEC = ex2f(dEC);                                              \
        float uOC = 1.0f + ex2f(seC) + ex2f(thC);                           \
        e0 = (mEA + emE) + lg2_poly(uEA);                                   \
        o0 = (mOA + emA) + lg2f(uOA);                                       \
        e1 = (mEB + emE) + lg2_poly(uEB);                                   \
        o1 = (mOB + emB) + lg2f(uOB);                                       \
        e2 = (mEC + emE) + lg2_poly(uEC);                                   \
        o2 = (mOC + emC) + lg2f(uOC);                                       \
    } while (0)

    int buf = 0;
    for (int b = 0; b < 249; b++) {
        stage_rows4(sEm, emn, 8 * b + 17, tid);
        asm volatile("cp.async.wait_group 2;\n" ::: "memory");
        if (l >= 24) {
            float* ex = &EX[buf][w][l - 24][0];
            ex[0] = e0; ex[1] = o0; ex[2] = e1;
            ex[3] = o1; ex[4] = e2; ex[5] = o2;
        }
        __syncthreads();
        if (w > 0 && l < 8) {
            const float* ex = &EX[buf][w - 1][l][0];
            e0 = ex[0]; o0 = ex[1]; e1 = ex[2];
            o1 = ex[3]; e2 = ex[4]; o2 = ex[5];
        }
        buf ^= 1;

        const int t0 = 8 * b + 1;
#pragma unroll
        for (int s = 0; s < 8; s++) DO_STEP(t0 + s);
    }

    // tail: t = 1993..1999 (7 steps)
    {
        asm volatile("cp.async.wait_group 0;\n" ::: "memory");
        if (l >= 24) {
            float* ex = &EX[buf][w][l - 24][0];
            ex[0] = e0; ex[1] = o0; ex[2] = e1;
            ex[3] = o1; ex[4] = e2; ex[5] = o2;
        }
        __syncthreads();
        if (w > 0 && l < 8) {
            const float* ex = &EX[buf][w - 1][l][0];
            e0 = ex[0]; o0 = ex[1]; e1 = ex[2];
            o1 = ex[3]; e2 = ex[4]; o2 = ex[5];
        }
#pragma unroll
        for (int s = 0; s < 7; s++) DO_STEP(1993 + s);
    }
#undef DO_STEP

    // collect final alphas (valid lanes: warp0 all; others l >= 7)
    if (w == 0 || l >= 7) {
        if (qA < 256) AF[qA] = make_float2(e0, o0);
        if (qB < 256) AF[qB] = make_float2(e1, o1);
        if (qC < 256) AF[qC] = make_float2(e2, o2);
    }
    __syncthreads();

    if (tid == 0) {
        float ea = AF[tlen].x;
        float eb = AF[(tlen >= 1) ? tlen - 1 : 0].y;
        float m = fmaxf(ea, eb);
        float l2 = m + lg2f(ex2f(ea - m) + ex2f(eb - m));
        g_loss[n] = -l2 * LN2;
        __threadfence();
        unsigned int tk = atomicAdd(&g_done, 1u);
        if (tk == NB - 1) {
            __threadfence();
            volatile float* gl = g_loss;
            float s = 0.0f;
            for (int i = 0; i < NB; i++) s += gl[i];
            d_out[0] = s * (1.0f / (float)NB);
        }
    }
}

// =====================================================================
extern "C" void kernel_launch(void* const* d_in, const int* in_sizes, int n_in,
                              void* d_out, int out_size) {
    const float* lp = (const float*)d_in[0];
    const int*   tg = (const int*)d_in[1];
    if (n_in >= 2 && in_sizes[0] == NB * CH * LL) {
        lp = (const float*)d_in[1];
        tg = (const int*)d_in[0];
    }

    k_nop<<<1, 32>>>();
    k_preprocess<<<NB, 256>>>(tg);
    dim3 g2((TT + TTILE - 1) / TTILE, NB);
    k_emission<<<g2, 128>>>(lp);
    k_ctc<<<NB, 128>>>((float*)d_out);
}